// round 11
// baseline (speedup 1.0000x reference)
#include <cuda_runtime.h>
#include <cuda_fp16.h>
#include <math.h>
#include <stdint.h>

#define NLVL    16
#define NPTS    (1 << 21)
#define TPB     256          // builder block size
#define MTPB    512          // main kernel block size (16 warps)
#define MAXQ    700000       // >= sum of res^2 over dense levels (683,431)
#define NSMEMQ  2283         // quads of levels 0..2 (289+625+1369), 36.5 KB
#define NITER   (NPTS / 64)  // 32768 point-batches of 64

// fp16 quad scratch: per dense cell, 4 corner float2s as 8 halves = 16B.
__device__ __align__(16) uint4 g_quad[MAXQ];

struct LP {
    float rm1[NLVL];
    int   res[NLVL];
    int   offs[NLVL];      // entry offset of level l in params table
    int   dense[NLVL];
    int   qoff[NLVL];      // quad-cell offset of level l in g_quad (dense only)
    int   pbase[NLVL + 1]; // cell-PAIR prefix base per dense level (builder)
};

static __device__ __forceinline__ uint4 pack_quad(float2 f00, float2 f10,
                                                  float2 f01, float2 f11)
{
    __half2 h00 = __floats2half2_rn(f00.x, f00.y);
    __half2 h10 = __floats2half2_rn(f10.x, f10.y);
    __half2 h01 = __floats2half2_rn(f01.x, f01.y);
    __half2 h11 = __floats2half2_rn(f11.x, f11.y);
    uint4 q;
    q.x = *reinterpret_cast<unsigned*>(&h00);
    q.y = *reinterpret_cast<unsigned*>(&h10);
    q.z = *reinterpret_cast<unsigned*>(&h01);
    q.w = *reinterpret_cast<unsigned*>(&h11);
    return q;
}

// ---------------- builder: 2 adjacent cells per thread (R9 winner) ---------
__global__ void __launch_bounds__(TPB) build_quads(
    const float2* __restrict__ tab, const LP lp, int npairs)
{
    int i = blockIdx.x * TPB + threadIdx.x;
    if (i >= npairs) return;

    int lvl = 0;
    #pragma unroll
    for (int l = 1; l < NLVL; l++)
        if (lp.dense[l] && i >= lp.pbase[l]) lvl = l;

    int j   = i - lp.pbase[lvl];
    int res = lp.res[lvl];
    int ppr = (res + 1) >> 1;          // cell pairs per row
    int gy  = j / ppr;
    int k   = j - gy * ppr;
    int gx  = k << 1;

    const float2* t = tab + lp.offs[lvl];
    int b = gy * res + gx;

    // Edge cells are never queried (xy < 0.95); over-reads stay in-bounds.
    float2 r00 = __ldg(t + b);
    float2 r01 = __ldg(t + b + 1);
    float2 r10 = __ldg(t + b + res);
    float2 r11 = __ldg(t + b + res + 1);

    int qi = lp.qoff[lvl] + gy * res + gx;
    g_quad[qi] = pack_quad(r00, r01, r10, r11);

    if (gx + 1 < res) {
        float2 r02 = __ldg(t + b + 2);
        float2 r12 = __ldg(t + b + res + 2);
        g_quad[qi + 1] = pack_quad(r01, r02, r11, r12);
    }
}

static __device__ __forceinline__ float2 lerp_quad(uint4 q, float wx, float wy)
{
    float2 f00 = __half22float2(*reinterpret_cast<__half2*>(&q.x));
    float2 f10 = __half22float2(*reinterpret_cast<__half2*>(&q.y));
    float2 f01 = __half22float2(*reinterpret_cast<__half2*>(&q.z));
    float2 f11 = __half22float2(*reinterpret_cast<__half2*>(&q.w));
    float ux = 1.0f - wx, uy = 1.0f - wy;
    float w00 = ux * uy, w10 = wx * uy, w01 = ux * wy, w11 = wx * wy;
    return make_float2(f00.x * w00 + f10.x * w10 + f01.x * w01 + f11.x * w11,
                       f00.y * w00 + f10.y * w10 + f01.y * w01 + f11.y * w11);
}

// ---------------- main kernel: persistent, smem-cached coarse levels -------
// 512 threads = 16 warps = two 8-warp groups; each group handles 32 points per
// batch exactly like the R5 winner (warp w: lanes 0-15 -> level 2w, 16-31 ->
// level 2w+1; 2 points/thread, class-uniform warps). Levels 0-2 quads are
// served from a per-CTA smem copy (divergent LDS: no L1 wavefronts, no L2
// sectors). Persistent grid (4 CTAs/SM) amortizes the 36.5 KB table load.
__global__ void __launch_bounds__(MTPB, 4) hashenc_kernel(
    const float2* __restrict__ xy,
    const float2* __restrict__ tab,
    float2*       __restrict__ out,
    const LP lp)
{
    __shared__ uint4  s_qtab[NSMEMQ];      // quads, levels 0..2 (36528 B)
    __shared__ float2 s_out[1024];         // [point 0..63][level 0..15], swizzled
    __shared__ float  s_rm1[NLVL];
    __shared__ int    s_res[NLVL], s_off[NLVL], s_dense[NLVL], s_qoff[NLVL];

    if (threadIdx.x < NLVL) {
        int t = threadIdx.x;
        s_rm1[t]   = lp.rm1[t];
        s_res[t]   = lp.res[t];
        s_off[t]   = lp.offs[t];
        s_dense[t] = lp.dense[t];
        s_qoff[t]  = lp.qoff[t];
    }
    // Preload coarse quad tables (g_quad[0..NSMEMQ) == levels 0..2).
    for (int i = threadIdx.x; i < NSMEMQ; i += MTPB)
        s_qtab[i] = g_quad[i];
    __syncthreads();

    unsigned wid   = threadIdx.x >> 5;
    unsigned lane  = threadIdx.x & 31u;
    unsigned group = wid >> 3;                      // 0 or 1 (32 points each)
    unsigned wg    = wid & 7u;                      // warp within group
    unsigned pt0   = (group << 5) | (lane & 15u);   // block-local point
    unsigned pt1   = pt0 + 16u;
    unsigned lvl   = (wg << 1) | (lane >> 4);       // level, class-uniform/warp

    float rm1 = s_rm1[lvl];
    int   res = s_res[lvl];
    int   dns = s_dense[lvl];
    int   qof = s_qoff[lvl];
    int   tof = s_off[lvl];

    for (unsigned blk = blockIdx.x; blk < NITER; blk += gridDim.x) {
        unsigned base = blk * 64u;

        float2 pA = __ldg(&xy[base + pt0]);         // broadcast: 2 lines/warp
        float2 pB = __ldg(&xy[base + pt1]);

        float pxA = fmaf(pA.x, rm1, 0.5f), pyA = fmaf(pA.y, rm1, 0.5f);
        float pxB = fmaf(pB.x, rm1, 0.5f), pyB = fmaf(pB.y, rm1, 0.5f);
        float fxA = floorf(pxA), fyA = floorf(pyA);
        float fxB = floorf(pxB), fyB = floorf(pyB);
        float wxA = pxA - fxA,  wyA = pyA - fyA;
        float wxB = pxB - fxB,  wyB = pyB - fyB;
        int gxA = (int)fxA, gyA = (int)fyA;
        int gxB = (int)fxB, gyB = (int)fyB;

        float2 oA, oB;

        if (lvl < 3u) {
            // Coarse dense: divergent LDS from smem quad table.
            uint4 qA = s_qtab[qof + gxA + gyA * res];
            uint4 qB = s_qtab[qof + gxB + gyB * res];
            oA = lerp_quad(qA, wxA, wyA);
            oB = lerp_quad(qB, wxB, wyB);
        } else if (dns) {
            // Dense: one 16B global quad load per point (MLP=2).
            const uint4* qb = &g_quad[qof];
            uint4 qA = __ldg(qb + gxA + gyA * res);
            uint4 qB = __ldg(qb + gxB + gyB * res);
            oA = lerp_quad(qA, wxA, wyA);
            oB = lerp_quad(qB, wxB, wyB);
        } else {
            const unsigned M  = (1u << 19) - 1u;    // hashed hsize is 2^19
            const float2* t  = tab + tof;
            const float4* t4 = (const float4*)t;

            unsigned h0A = (unsigned)gyA       * 2654435761u;
            unsigned h1A = (unsigned)(gyA + 1) * 2654435761u;
            int a00 = (int)(((unsigned)gxA       ^ h0A) & M);
            int a10 = (int)(((unsigned)(gxA + 1) ^ h0A) & M);
            int a01 = (int)(((unsigned)gxA       ^ h1A) & M);
            int a11 = (int)(((unsigned)(gxA + 1) ^ h1A) & M);

            unsigned h0B = (unsigned)gyB       * 2654435761u;
            unsigned h1B = (unsigned)(gyB + 1) * 2654435761u;
            int b00 = (int)(((unsigned)gxB       ^ h0B) & M);
            int b10 = (int)(((unsigned)(gxB + 1) ^ h0B) & M);
            int b01 = (int)(((unsigned)gxB       ^ h1B) & M);
            int b11 = (int)(((unsigned)(gxB + 1) ^ h1B) & M);

            float2 A00, A10, A01, A11, B00, B10, B01, B11;

            if ((gxA & 1) == 0) {                   // aligned pairs {2k,2k+1}
                float4 r0 = __ldg(t4 + (a00 >> 1));
                float4 r1 = __ldg(t4 + (a01 >> 1));
                if (a00 & 1) { A00 = make_float2(r0.z, r0.w); A10 = make_float2(r0.x, r0.y); }
                else         { A00 = make_float2(r0.x, r0.y); A10 = make_float2(r0.z, r0.w); }
                if (a01 & 1) { A01 = make_float2(r1.z, r1.w); A11 = make_float2(r1.x, r1.y); }
                else         { A01 = make_float2(r1.x, r1.y); A11 = make_float2(r1.z, r1.w); }
            } else {
                A00 = __ldg(t + a00);
                A10 = __ldg(t + a10);
                A01 = __ldg(t + a01);
                A11 = __ldg(t + a11);
            }
            if ((gxB & 1) == 0) {
                float4 r0 = __ldg(t4 + (b00 >> 1));
                float4 r1 = __ldg(t4 + (b01 >> 1));
                if (b00 & 1) { B00 = make_float2(r0.z, r0.w); B10 = make_float2(r0.x, r0.y); }
                else         { B00 = make_float2(r0.x, r0.y); B10 = make_float2(r0.z, r0.w); }
                if (b01 & 1) { B01 = make_float2(r1.z, r1.w); B11 = make_float2(r1.x, r1.y); }
                else         { B01 = make_float2(r1.x, r1.y); B11 = make_float2(r1.z, r1.w); }
            } else {
                B00 = __ldg(t + b00);
                B10 = __ldg(t + b10);
                B01 = __ldg(t + b01);
                B11 = __ldg(t + b11);
            }

            {
                float ux = 1.0f - wxA, uy = 1.0f - wyA;
                float w00 = ux * uy, w10 = wxA * uy, w01 = ux * wyA, w11 = wxA * wyA;
                oA = make_float2(A00.x * w00 + A10.x * w10 + A01.x * w01 + A11.x * w11,
                                 A00.y * w00 + A10.y * w10 + A01.y * w01 + A11.y * w11);
            }
            {
                float ux = 1.0f - wxB, uy = 1.0f - wyB;
                float w00 = ux * uy, w10 = wxB * uy, w01 = ux * wyB, w11 = wxB * wyB;
                oB = make_float2(B00.x * w00 + B10.x * w10 + B01.x * w01 + B11.x * w11,
                                 B00.y * w00 + B10.y * w10 + B01.y * w01 + B11.y * w11);
            }
        }

        s_out[pt0 * 16 + ((lvl + pt0) & 15u)] = oA;
        s_out[pt1 * 16 + ((lvl + pt1) & 15u)] = oB;
        __syncthreads();

        // Coalesced flush: 1024 float2 per batch, 2 per thread.
        float2* ob = out + blk * 1024u;
        #pragma unroll
        for (int k = 0; k < 2; k++) {
            unsigned t  = threadIdx.x + k * (unsigned)MTPB;
            unsigned tp = t >> 4;
            unsigned tl = t & 15u;
            ob[t] = s_out[tp * 16 + ((tl + tp) & 15u)];
        }
        __syncthreads();   // s_out reused next iteration
    }
}

extern "C" void kernel_launch(void* const* d_in, const int* in_sizes, int n_in,
                              void* d_out, int out_size)
{
    (void)in_sizes; (void)n_in; (void)out_size;

    // Mirror the reference's level-geometry computation exactly (same libm).
    LP lp;
    long long sizes[NLVL];
    int       resv [NLVL];
    double log2s = log2(1.5);
    long long off = 0;
    for (int l = 0; l < NLVL; l++) {
        double scale = pow(2.0, (double)l * log2s) * 16.0 - 1.0;
        int r = (int)ceil(scale) + 1;
        long long sz = (((long long)r * (long long)r + 7) / 8) * 8;
        if (sz > (1LL << 19)) sz = (1LL << 19);
        resv[l]    = r;
        sizes[l]   = sz;
        lp.rm1[l]  = (float)(r - 1);
        lp.res[l]  = r;
        lp.offs[l] = (int)off;
        off += sz;
    }
    int qoff = 0, npairs = 0;
    for (int l = 0; l < NLVL; l++) {
        lp.dense[l] = (sizes[l] >= (long long)resv[l] * resv[l]) ? 1 : 0;
        lp.qoff[l]  = 0;
        lp.pbase[l] = npairs;
        if (lp.dense[l]) {
            lp.qoff[l] = qoff;
            qoff   += resv[l] * resv[l];
            npairs += resv[l] * ((resv[l] + 1) >> 1);
        }
    }
    lp.pbase[NLVL] = npairs;

    const float2* xy  = (const float2*)d_in[0];
    const float2* tab = (const float2*)d_in[1];
    float2*       out = (float2*)d_out;

    int smCount = 148;
    cudaDeviceGetAttribute(&smCount, cudaDevAttrMultiProcessorCount, 0);
    int grid = 4 * smCount;                        // 4 CTAs/SM, persistent
    if (grid > NITER) grid = NITER;

    build_quads<<<(npairs + TPB - 1) / TPB, TPB>>>(tab, lp, npairs);
    hashenc_kernel<<<grid, MTPB>>>(xy, tab, out, lp);
}

// round 12
// speedup vs baseline: 1.1867x; 1.1867x over previous
#include <cuda_runtime.h>
#include <cuda_fp16.h>
#include <math.h>
#include <stdint.h>

#define NLVL   16
#define NPTS   (1 << 21)
#define TPB    256
#define MAXQ   700000      // >= sum of res^2 over dense levels (683,431)

// fp16 quad scratch: per dense cell, 4 corner float2s as 8 halves = 16B.
__device__ __align__(16) uint4 g_quad[MAXQ];

struct LP {
    float rm1[NLVL];
    int   res[NLVL];
    int   offs[NLVL];      // entry offset of level l in params table
    int   dense[NLVL];
    int   qoff[NLVL];      // quad-cell offset of level l in g_quad (dense only)
    int   pbase[NLVL + 1]; // 2x2-tile prefix base per dense level (builder)
};

static __device__ __forceinline__ uint4 pack_quad(float2 f00, float2 f10,
                                                  float2 f01, float2 f11)
{
    __half2 h00 = __floats2half2_rn(f00.x, f00.y);
    __half2 h10 = __floats2half2_rn(f10.x, f10.y);
    __half2 h01 = __floats2half2_rn(f01.x, f01.y);
    __half2 h11 = __floats2half2_rn(f11.x, f11.y);
    uint4 q;
    q.x = *reinterpret_cast<unsigned*>(&h00);
    q.y = *reinterpret_cast<unsigned*>(&h10);
    q.z = *reinterpret_cast<unsigned*>(&h01);
    q.w = *reinterpret_cast<unsigned*>(&h11);
    return q;
}

// ---------------- builder: 2x2 cells per thread -----------------------------
// Thread handles cells (2k..2k+1, 2m..2m+1): 9 corner loads -> 4 quads
// (vs 12 loads with pair-threads). Flattened 1-D grid via pbase prefix.
__global__ void __launch_bounds__(TPB) build_quads(
    const float2* __restrict__ tab, const LP lp, int npairs)
{
    int i = blockIdx.x * TPB + threadIdx.x;
    if (i >= npairs) return;

    int lvl = 0;
    #pragma unroll
    for (int l = 1; l < NLVL; l++)
        if (lp.dense[l] && i >= lp.pbase[l]) lvl = l;

    int j   = i - lp.pbase[lvl];
    int res = lp.res[lvl];
    int hpr = (res + 1) >> 1;          // 2x2 tiles per row
    int m   = j / hpr;
    int k   = j - m * hpr;
    int gx  = k << 1;
    int gy  = m << 1;

    const float2* t = tab + lp.offs[lvl];
    int b = gy * res + gx;

    // 3x3 corner block. Queried cells (gx,gy <= res-2) read strictly in-level;
    // edge-tile over-reads land in later levels' table space (still in params).
    float2 r[3][3];
    #pragma unroll
    for (int dy = 0; dy < 3; dy++)
        #pragma unroll
        for (int dx = 0; dx < 3; dx++)
            r[dy][dx] = __ldg(t + b + dy * res + dx);

    int  qi  = lp.qoff[lvl] + gy * res + gx;
    bool xok = (gx + 1 < res);
    bool yok = (gy + 1 < res);

    g_quad[qi] = pack_quad(r[0][0], r[0][1], r[1][0], r[1][1]);
    if (xok) g_quad[qi + 1] = pack_quad(r[0][1], r[0][2], r[1][1], r[1][2]);
    if (yok) {
        g_quad[qi + res] = pack_quad(r[1][0], r[1][1], r[2][0], r[2][1]);
        if (xok) g_quad[qi + res + 1] = pack_quad(r[1][1], r[1][2], r[2][1], r[2][2]);
    }
}

// ---------------- main kernel (exact R9/R5 winner) --------------------------
// Block = 256 threads = 8 warps, 32 points per block, 2 points per thread.
// Warp w: lanes 0-15 -> level 2w, lanes 16-31 -> level 2w+1 (class-uniform:
// warps 0-4 all dense, warps 5-7 all hashed). Each lane processes points
// {pt, pt+16} -> 2 independent gathers in flight per thread (MLP=2+).
// Results staged in smem (swizzled) and flushed coalesced.
__global__ void __launch_bounds__(TPB) hashenc_kernel(
    const float2* __restrict__ xy,
    const float2* __restrict__ tab,
    float2*       __restrict__ out,
    const LP lp)
{
    __shared__ float  s_rm1[NLVL];
    __shared__ int    s_res[NLVL], s_off[NLVL], s_dense[NLVL], s_qoff[NLVL];
    __shared__ float2 s_out[512];          // [point 0..31][level 0..15], swizzled

    if (threadIdx.x < NLVL) {
        int t = threadIdx.x;
        s_rm1[t]   = lp.rm1[t];
        s_res[t]   = lp.res[t];
        s_off[t]   = lp.offs[t];
        s_dense[t] = lp.dense[t];
        s_qoff[t]  = lp.qoff[t];
    }
    __syncthreads();

    unsigned wid  = threadIdx.x >> 5;
    unsigned lane = threadIdx.x & 31u;
    unsigned pt0  = lane & 15u;                     // local point 0..15
    unsigned pt1  = pt0 + 16u;                      // local point 16..31
    unsigned lvl  = (wid << 1) | (lane >> 4);       // level, class-uniform/warp

    unsigned base  = blockIdx.x * 32u;

    float2 pA = __ldg(&xy[base + pt0]);             // broadcast: 1 line/warp
    float2 pB = __ldg(&xy[base + pt1]);

    float rm1 = s_rm1[lvl];
    int   res = s_res[lvl];

    float pxA = fmaf(pA.x, rm1, 0.5f), pyA = fmaf(pA.y, rm1, 0.5f);
    float pxB = fmaf(pB.x, rm1, 0.5f), pyB = fmaf(pB.y, rm1, 0.5f);
    float fxA = floorf(pxA), fyA = floorf(pyA);
    float fxB = floorf(pxB), fyB = floorf(pyB);
    float wxA = pxA - fxA,  wyA = pyA - fyA;
    float wxB = pxB - fxB,  wyB = pyB - fyB;
    int gxA = (int)fxA, gyA = (int)fyA;
    int gxB = (int)fxB, gyB = (int)fyB;

    float2 A00, A10, A01, A11;
    float2 B00, B10, B01, B11;

    if (s_dense[lvl]) {                             // uniform across the warp
        // Two independent 16B quad loads issued back-to-back (MLP=2).
        const uint4* qb = &g_quad[s_qoff[lvl]];
        uint4 qA = __ldg(qb + gxA + gyA * res);
        uint4 qB = __ldg(qb + gxB + gyB * res);
        A00 = __half22float2(*reinterpret_cast<__half2*>(&qA.x));
        A10 = __half22float2(*reinterpret_cast<__half2*>(&qA.y));
        A01 = __half22float2(*reinterpret_cast<__half2*>(&qA.z));
        A11 = __half22float2(*reinterpret_cast<__half2*>(&qA.w));
        B00 = __half22float2(*reinterpret_cast<__half2*>(&qB.x));
        B10 = __half22float2(*reinterpret_cast<__half2*>(&qB.y));
        B01 = __half22float2(*reinterpret_cast<__half2*>(&qB.z));
        B11 = __half22float2(*reinterpret_cast<__half2*>(&qB.w));
    } else {
        const unsigned M  = (1u << 19) - 1u;        // hashed hsize is 2^19
        const float2* t  = tab + s_off[lvl];
        const float4* t4 = (const float4*)t;

        unsigned h0A = (unsigned)gyA       * 2654435761u;
        unsigned h1A = (unsigned)(gyA + 1) * 2654435761u;
        int a00 = (int)(((unsigned)gxA       ^ h0A) & M);
        int a10 = (int)(((unsigned)(gxA + 1) ^ h0A) & M);
        int a01 = (int)(((unsigned)gxA       ^ h1A) & M);
        int a11 = (int)(((unsigned)(gxA + 1) ^ h1A) & M);

        unsigned h0B = (unsigned)gyB       * 2654435761u;
        unsigned h1B = (unsigned)(gyB + 1) * 2654435761u;
        int b00 = (int)(((unsigned)gxB       ^ h0B) & M);
        int b10 = (int)(((unsigned)(gxB + 1) ^ h0B) & M);
        int b01 = (int)(((unsigned)gxB       ^ h1B) & M);
        int b11 = (int)(((unsigned)(gxB + 1) ^ h1B) & M);

        // Point A rows: gx even <=> both rows' x-pairs aligned {2k,2k+1}.
        if ((gxA & 1) == 0) {
            float4 r0 = __ldg(t4 + (a00 >> 1));
            float4 r1 = __ldg(t4 + (a01 >> 1));
            if (a00 & 1) { A00 = make_float2(r0.z, r0.w); A10 = make_float2(r0.x, r0.y); }
            else         { A00 = make_float2(r0.x, r0.y); A10 = make_float2(r0.z, r0.w); }
            if (a01 & 1) { A01 = make_float2(r1.z, r1.w); A11 = make_float2(r1.x, r1.y); }
            else         { A01 = make_float2(r1.x, r1.y); A11 = make_float2(r1.z, r1.w); }
        } else {
            A00 = __ldg(t + a00);
            A10 = __ldg(t + a10);
            A01 = __ldg(t + a01);
            A11 = __ldg(t + a11);
        }
        // Point B rows
        if ((gxB & 1) == 0) {
            float4 r0 = __ldg(t4 + (b00 >> 1));
            float4 r1 = __ldg(t4 + (b01 >> 1));
            if (b00 & 1) { B00 = make_float2(r0.z, r0.w); B10 = make_float2(r0.x, r0.y); }
            else         { B00 = make_float2(r0.x, r0.y); B10 = make_float2(r0.z, r0.w); }
            if (b01 & 1) { B01 = make_float2(r1.z, r1.w); B11 = make_float2(r1.x, r1.y); }
            else         { B01 = make_float2(r1.x, r1.y); B11 = make_float2(r1.z, r1.w); }
        } else {
            B00 = __ldg(t + b00);
            B10 = __ldg(t + b10);
            B01 = __ldg(t + b01);
            B11 = __ldg(t + b11);
        }
    }

    {
        float ux = 1.0f - wxA, uy = 1.0f - wyA;
        float w00 = ux * uy, w10 = wxA * uy, w01 = ux * wyA, w11 = wxA * wyA;
        float ox = A00.x * w00 + A10.x * w10 + A01.x * w01 + A11.x * w11;
        float oy = A00.y * w00 + A10.y * w10 + A01.y * w01 + A11.y * w11;
        s_out[pt0 * 16 + ((lvl + pt0) & 15u)] = make_float2(ox, oy);
    }
    {
        float ux = 1.0f - wxB, uy = 1.0f - wyB;
        float w00 = ux * uy, w10 = wxB * uy, w01 = ux * wyB, w11 = wxB * wyB;
        float ox = B00.x * w00 + B10.x * w10 + B01.x * w01 + B11.x * w11;
        float oy = B00.y * w00 + B10.y * w10 + B01.y * w01 + B11.y * w11;
        s_out[pt1 * 16 + ((lvl + pt1) & 15u)] = make_float2(ox, oy);
    }
    __syncthreads();

    // Coalesced flush: 512 float2 per block, 2 per thread.
    float2* ob = out + blockIdx.x * 512u;
    #pragma unroll
    for (int k = 0; k < 2; k++) {
        unsigned t  = threadIdx.x + k * 256u;
        unsigned tp = t >> 4;
        unsigned tl = t & 15u;
        ob[t] = s_out[tp * 16 + ((tl + tp) & 15u)];
    }
}

extern "C" void kernel_launch(void* const* d_in, const int* in_sizes, int n_in,
                              void* d_out, int out_size)
{
    (void)in_sizes; (void)n_in; (void)out_size;

    // Mirror the reference's level-geometry computation exactly (same libm).
    LP lp;
    long long sizes[NLVL];
    int       resv [NLVL];
    double log2s = log2(1.5);
    long long off = 0;
    for (int l = 0; l < NLVL; l++) {
        double scale = pow(2.0, (double)l * log2s) * 16.0 - 1.0;
        int r = (int)ceil(scale) + 1;
        long long sz = (((long long)r * (long long)r + 7) / 8) * 8;
        if (sz > (1LL << 19)) sz = (1LL << 19);
        resv[l]    = r;
        sizes[l]   = sz;
        lp.rm1[l]  = (float)(r - 1);
        lp.res[l]  = r;
        lp.offs[l] = (int)off;
        off += sz;
    }
    int qoff = 0, npairs = 0;
    for (int l = 0; l < NLVL; l++) {
        lp.dense[l] = (sizes[l] >= (long long)resv[l] * resv[l]) ? 1 : 0;
        lp.qoff[l]  = 0;
        lp.pbase[l] = npairs;
        if (lp.dense[l]) {
            lp.qoff[l] = qoff;
            qoff += resv[l] * resv[l];
            int hpr = (resv[l] + 1) >> 1;           // 2x2 tiles per row/col
            npairs += hpr * hpr;
        }
    }
    lp.pbase[NLVL] = npairs;

    const float2* xy  = (const float2*)d_in[0];
    const float2* tab = (const float2*)d_in[1];
    float2*       out = (float2*)d_out;

    build_quads<<<(npairs + TPB - 1) / TPB, TPB>>>(tab, lp, npairs);
    hashenc_kernel<<<NPTS / 32, TPB>>>(xy, tab, out, lp);
}